// round 14
// baseline (speedup 1.0000x reference)
#include <cuda_runtime.h>
#include <stdint.h>

// B=128, N=256, T=1024, C=10
#define T_LEN   1024
#define N_NEUR  256
#define C_GAP   10
#define WPB     16               // warps (= rows) per block
#define THREADS (WPB * 32)       // 512
#define NEGINF  (-3.402823466e38f)
#define FULL    0xffffffffu
#define MAXCL   96               // max clusters per row = ceil(1024/11)+1

__device__ float    g_loss;     // zero-init; reset by last block each launch
__device__ unsigned g_tick;

__global__ __launch_bounds__(THREADS)
void stca_main(const float* __restrict__ vmem,
               const int*   __restrict__ labels,
               float*       __restrict__ out)
{
    __shared__ unsigned sh_b[WPB][32];       // per-window ballots
    __shared__ unsigned sh_cl[WPB][MAXCL];   // (spikesBefore<<16)|startPos
    __shared__ float    warp_contrib[WPB];

    const int tid = threadIdx.x;
    const int w   = tid >> 5;
    const int l   = tid & 31;
    const bool lane0 = (l == 0);
    const int row = blockIdx.x * WPB + w;
    const float* rp = vmem + (size_t)row * T_LEN;

    // ---- Phase 1: single coalesced pass. Ballots -> per-window spike masks.
    //      (R4's exact loop: plain LDG + ballot; ptxas front-batches the loads.)
    float maxall = NEGINF;
    #pragma unroll
    for (int k = 0; k < 32; ++k) {
        float x = __ldg(rp + k * 32 + l);
        maxall = fmaxf(maxall, x);
        unsigned b = __ballot_sync(FULL, x >= 0.0f);
        if (lane0) sh_b[w][k] = b;
    }
    __syncwarp();
    unsigned m = sh_b[w][l];                 // spike mask of window [32l, 32l+32)

    // ---- Global cluster-start mask: spike with no spike in previous C steps.
    unsigned prev = __shfl_up_sync(FULL, m, 1);
    if (lane0) prev = 0;
    unsigned long long A  = ((unsigned long long)m << 32) | prev;
    unsigned long long t1 = (A << 1) | (A << 2);          // shifts {1,2}
    unsigned long long t2 = t1 | (t1 << 2);               // {1..4}
    unsigned long long t3 = t2 | (t2 << 4);               // {1..8}
    unsigned long long sp = t3 | (t1 << 8);               // {1..10}
    unsigned starts = m & ~(unsigned)(sp >> 32);

    const int sc = __popc(starts);
    const int nc = __reduce_add_sync(FULL, sc);

    const int b_     = row >> 8;
    const int nn     = row & (N_NEUR - 1);
    const int target = (__ldg(labels + b_) == nn) ? 1 : 0;

    float contrib = 0.0f;
    if (nc > target) {                       // warp-uniform
        if (nc == 1) {
            // single cluster: span max == row max (spikes >= 0, rest < 0)
            #pragma unroll
            for (int d = 16; d > 0; d >>= 1)
                maxall = fmaxf(maxall, __shfl_xor_sync(FULL, maxall, d));
            contrib = maxall;
        } else {
            // ---- cluster table: (spikes before start, start pos)
            const int pc = __popc(m);
            int ipc = pc, isc = sc;          // inclusive scans
            #pragma unroll
            for (int d = 1; d < 32; d <<= 1) {
                int vp = __shfl_up_sync(FULL, ipc, d);
                int vs = __shfl_up_sync(FULL, isc, d);
                if (l >= d) { ipc += vp; isc += vs; }
            }
            const int excl  = ipc - pc;      // spikes before my window
            int c           = isc - sc;      // clusters before my window
            const int S_tot = __shfl_sync(FULL, ipc, 31);

            unsigned sm_ = starts;
            const int tb = l * 32;
            while (sm_) {
                int bit = __ffs(sm_) - 1;
                sm_ &= sm_ - 1;
                int sb = excl + __popc(m & ((1u << bit) - 1u));
                sh_cl[w][c] = ((unsigned)sb << 16) | (unsigned)(tb + bit);
                ++c;
            }
            if (lane0) sh_cl[w][nc] = ((unsigned)S_tot << 16) | (unsigned)T_LEN;
            __syncwarp();

            // smallest cluster, earliest on ties: min over (size<<7 | idx)
            int best = 0x7fffffff;
            for (int c0 = l; c0 < nc; c0 += 32) {
                unsigned a  = sh_cl[w][c0];
                unsigned bn = sh_cl[w][c0 + 1];
                int size = (int)(bn >> 16) - (int)(a >> 16);
                best = min(best, (size << 7) | c0);
            }
            best = __reduce_min_sync(FULL, (unsigned)best);
            const int cstar = best & 127;
            const unsigned a  = sh_cl[w][cstar];
            const unsigned bn = sh_cl[w][cstar + 1];
            const int cb  = (int)(a  & 0xffffu);
            const int ceN = (int)(bn & 0xffffu);     // exclusive end
            const unsigned width = (unsigned)(ceN - cb);

            // re-read only float4 blocks overlapping [cb, ceN) — cache hits, rare
            const float4* g4 = (const float4*)rp;
            float smax = NEGINF;
            const int ks = cb >> 7, ke = (ceN - 1) >> 7;
            for (int k = ks; k <= ke; ++k) {
                float4 v = __ldg(g4 + k * 32 + l);
                int t0 = k * 128 + 4 * l;
                if ((unsigned)(t0     - cb) < width) smax = fmaxf(smax, v.x);
                if ((unsigned)(t0 + 1 - cb) < width) smax = fmaxf(smax, v.y);
                if ((unsigned)(t0 + 2 - cb) < width) smax = fmaxf(smax, v.z);
                if ((unsigned)(t0 + 3 - cb) < width) smax = fmaxf(smax, v.w);
            }
            #pragma unroll
            for (int d = 16; d > 0; d >>= 1)
                smax = fmaxf(smax, __shfl_xor_sync(FULL, smax, d));
            contrib = smax;
        }
    } else if (nc == 0 && target) {
        #pragma unroll
        for (int d = 16; d > 0; d >>= 1)
            maxall = fmaxf(maxall, __shfl_xor_sync(FULL, maxall, d));
        contrib = -maxall;
    }

    if (lane0) {
        out[1 + row] = (float)nc;            // spike_output
        warp_contrib[w] = contrib;
    }
    __syncthreads();

    // ---- grid reduction: device accumulator + ticket (graph-replay safe,
    //      single kernel — no separate zeroing launch)
    if (tid == 0) {
        float s = 0.0f;
        #pragma unroll
        for (int i = 0; i < WPB; ++i) s += warp_contrib[i];
        atomicAdd(&g_loss, s);
        __threadfence();
        unsigned t = atomicAdd(&g_tick, 1u);
        if (t == gridDim.x - 1) {            // last block: publish + reset
            __threadfence();
            out[0] = g_loss;
            g_loss = 0.0f;
            g_tick = 0u;
        }
    }
}

extern "C" void kernel_launch(void* const* d_in, const int* in_sizes, int n_in,
                              void* d_out, int out_size) {
    const float* vmem   = (const float*)d_in[0];   // [128,256,1024] f32
    // d_in[1] = vlastmem — unused by the reference forward; deliberately not read
    const int*   labels = (const int*)d_in[2];     // [128] i32
    float*       out    = (float*)d_out;           // [1 + 128*256] f32

    const int total_rows = 128 * 256;              // 32768
    stca_main<<<total_rows / WPB, THREADS>>>(vmem, labels, out);
}

// round 15
// speedup vs baseline: 1.0674x; 1.0674x over previous
#include <cuda_runtime.h>
#include <stdint.h>

// B=128, N=256, T=1024, C=10
#define T_LEN   1024
#define N_NEUR  256
#define C_GAP   10
#define WPB     8                // warps (= rows) per block — measured optimum
#define THREADS (WPB * 32)
#define NEGINF  (-3.402823466e38f)
#define FULL    0xffffffffu
#define MAXCL   96               // max clusters per row = ceil(1024/11)+1

__device__ float    g_loss;     // zero-init; reset by last block each launch
__device__ unsigned g_tick;

__global__ __launch_bounds__(THREADS)
void stca_main(const float* __restrict__ vmem,
               const int*   __restrict__ labels,
               float*       __restrict__ out)
{
    __shared__ unsigned sh_b[WPB][32];       // per-window ballots
    __shared__ unsigned sh_cl[WPB][MAXCL];   // (spikesBefore<<16)|startPos
    __shared__ float    warp_contrib[WPB];

    const int tid = threadIdx.x;
    const int w   = tid >> 5;
    const int l   = tid & 31;
    const bool lane0 = (l == 0);
    const int row = blockIdx.x * WPB + w;
    const float* rp = vmem + (size_t)row * T_LEN;

    // ---- Phase 1: single coalesced pass. Ballots -> per-window spike masks.
    //      Plain LDG + ballot; ptxas front-batches the loads (measured optimum).
    float maxall = NEGINF;
    #pragma unroll
    for (int k = 0; k < 32; ++k) {
        float x = __ldg(rp + k * 32 + l);
        maxall = fmaxf(maxall, x);
        unsigned b = __ballot_sync(FULL, x >= 0.0f);
        if (lane0) sh_b[w][k] = b;
    }
    __syncwarp();
    unsigned m = sh_b[w][l];                 // spike mask of window [32l, 32l+32)

    // ---- Global cluster-start mask: spike with no spike in previous C steps.
    unsigned prev = __shfl_up_sync(FULL, m, 1);
    if (lane0) prev = 0;
    unsigned long long A  = ((unsigned long long)m << 32) | prev;
    unsigned long long t1 = (A << 1) | (A << 2);          // shifts {1,2}
    unsigned long long t2 = t1 | (t1 << 2);               // {1..4}
    unsigned long long t3 = t2 | (t2 << 4);               // {1..8}
    unsigned long long sp = t3 | (t1 << 8);               // {1..10}
    unsigned starts = m & ~(unsigned)(sp >> 32);

    const int sc = __popc(starts);
    const int nc = __reduce_add_sync(FULL, sc);

    const int b_     = row >> 8;
    const int nn     = row & (N_NEUR - 1);
    const int target = (__ldg(labels + b_) == nn) ? 1 : 0;

    float contrib = 0.0f;
    if (nc > target) {                       // warp-uniform
        if (nc == 1) {
            // single cluster: span max == row max (spikes >= 0, rest < 0)
            #pragma unroll
            for (int d = 16; d > 0; d >>= 1)
                maxall = fmaxf(maxall, __shfl_xor_sync(FULL, maxall, d));
            contrib = maxall;
        } else {
            // ---- cluster table: (spikes before start, start pos)
            const int pc = __popc(m);
            int ipc = pc, isc = sc;          // inclusive scans
            #pragma unroll
            for (int d = 1; d < 32; d <<= 1) {
                int vp = __shfl_up_sync(FULL, ipc, d);
                int vs = __shfl_up_sync(FULL, isc, d);
                if (l >= d) { ipc += vp; isc += vs; }
            }
            const int excl  = ipc - pc;      // spikes before my window
            int c           = isc - sc;      // clusters before my window
            const int S_tot = __shfl_sync(FULL, ipc, 31);

            unsigned sm_ = starts;
            const int tb = l * 32;
            while (sm_) {
                int bit = __ffs(sm_) - 1;
                sm_ &= sm_ - 1;
                int sb = excl + __popc(m & ((1u << bit) - 1u));
                sh_cl[w][c] = ((unsigned)sb << 16) | (unsigned)(tb + bit);
                ++c;
            }
            if (lane0) sh_cl[w][nc] = ((unsigned)S_tot << 16) | (unsigned)T_LEN;
            __syncwarp();

            // smallest cluster, earliest on ties: min over (size<<7 | idx)
            int best = 0x7fffffff;
            for (int c0 = l; c0 < nc; c0 += 32) {
                unsigned a  = sh_cl[w][c0];
                unsigned bn = sh_cl[w][c0 + 1];
                int size = (int)(bn >> 16) - (int)(a >> 16);
                best = min(best, (size << 7) | c0);
            }
            best = __reduce_min_sync(FULL, (unsigned)best);
            const int cstar = best & 127;
            const unsigned a  = sh_cl[w][cstar];
            const unsigned bn = sh_cl[w][cstar + 1];
            const int cb  = (int)(a  & 0xffffu);
            const int ceN = (int)(bn & 0xffffu);     // exclusive end
            const unsigned width = (unsigned)(ceN - cb);

            // re-read only float4 blocks overlapping [cb, ceN) — cache hits, rare
            const float4* g4 = (const float4*)rp;
            float smax = NEGINF;
            const int ks = cb >> 7, ke = (ceN - 1) >> 7;
            for (int k = ks; k <= ke; ++k) {
                float4 v = __ldg(g4 + k * 32 + l);
                int t0 = k * 128 + 4 * l;
                if ((unsigned)(t0     - cb) < width) smax = fmaxf(smax, v.x);
                if ((unsigned)(t0 + 1 - cb) < width) smax = fmaxf(smax, v.y);
                if ((unsigned)(t0 + 2 - cb) < width) smax = fmaxf(smax, v.z);
                if ((unsigned)(t0 + 3 - cb) < width) smax = fmaxf(smax, v.w);
            }
            #pragma unroll
            for (int d = 16; d > 0; d >>= 1)
                smax = fmaxf(smax, __shfl_xor_sync(FULL, smax, d));
            contrib = smax;
        }
    } else if (nc == 0 && target) {
        #pragma unroll
        for (int d = 16; d > 0; d >>= 1)
            maxall = fmaxf(maxall, __shfl_xor_sync(FULL, maxall, d));
        contrib = -maxall;
    }

    if (lane0) {
        out[1 + row] = (float)nc;            // spike_output
        warp_contrib[w] = contrib;
    }
    __syncthreads();

    // ---- grid reduction: device accumulator + ticket (graph-replay safe,
    //      single kernel — no separate zeroing launch)
    if (tid == 0) {
        float s = 0.0f;
        #pragma unroll
        for (int i = 0; i < WPB; ++i) s += warp_contrib[i];
        atomicAdd(&g_loss, s);
        __threadfence();
        unsigned t = atomicAdd(&g_tick, 1u);
        if (t == gridDim.x - 1) {            // last block: publish + reset
            __threadfence();
            out[0] = g_loss;
            g_loss = 0.0f;
            g_tick = 0u;
        }
    }
}

extern "C" void kernel_launch(void* const* d_in, const int* in_sizes, int n_in,
                              void* d_out, int out_size) {
    const float* vmem   = (const float*)d_in[0];   // [128,256,1024] f32
    // d_in[1] = vlastmem — unused by the reference forward; deliberately not read
    const int*   labels = (const int*)d_in[2];     // [128] i32
    float*       out    = (float*)d_out;           // [1 + 128*256] f32

    const int total_rows = 128 * 256;              // 32768
    stca_main<<<total_rows / WPB, THREADS>>>(vmem, labels, out);
}

// round 16
// speedup vs baseline: 1.1594x; 1.0862x over previous
#include <cuda_runtime.h>
#include <stdint.h>

// B=128, N=256, T=1024, C=10
#define T_LEN   1024
#define N_NEUR  256
#define C_GAP   10
#define WPB     8                // warps (= rows) per block — measured optimum
#define THREADS (WPB * 32)
#define NEGINF  (-3.402823466e38f)
#define FULL    0xffffffffu
#define MAXCL   96               // max clusters per row = ceil(1024/11)+1

__device__ float    g_loss;     // zero-init; reset by last block each launch
__device__ unsigned g_tick;

__global__ __launch_bounds__(THREADS)
void stca_main(const float* __restrict__ vmem,
               const int*   __restrict__ labels,
               float*       __restrict__ out)
{
    __shared__ unsigned sh_b[WPB][32];       // per-window ballots
    __shared__ unsigned sh_cl[WPB][MAXCL];   // (spikesBefore<<16)|startPos
    __shared__ float    warp_contrib[WPB];

    const int tid = threadIdx.x;
    const int w   = tid >> 5;
    const int l   = tid & 31;
    const bool lane0 = (l == 0);
    const int row = blockIdx.x * WPB + w;
    const float* rp = vmem + (size_t)row * T_LEN;

    // ---- Phase 1: single coalesced pass. Ballots -> per-window spike masks.
    //      Plain load + ballot (measured optimum); evict-first streaming hint
    //      since the 128MB stream is read-once and exactly thrashes L2.
    float maxall = NEGINF;
    #pragma unroll
    for (int k = 0; k < 32; ++k) {
        float x = __ldcs(rp + k * 32 + l);
        maxall = fmaxf(maxall, x);
        unsigned b = __ballot_sync(FULL, x >= 0.0f);
        if (lane0) sh_b[w][k] = b;
    }
    __syncwarp();
    unsigned m = sh_b[w][l];                 // spike mask of window [32l, 32l+32)

    // ---- Global cluster-start mask: spike with no spike in previous C steps.
    unsigned prev = __shfl_up_sync(FULL, m, 1);
    if (lane0) prev = 0;
    unsigned long long A  = ((unsigned long long)m << 32) | prev;
    unsigned long long t1 = (A << 1) | (A << 2);          // shifts {1,2}
    unsigned long long t2 = t1 | (t1 << 2);               // {1..4}
    unsigned long long t3 = t2 | (t2 << 4);               // {1..8}
    unsigned long long sp = t3 | (t1 << 8);               // {1..10}
    unsigned starts = m & ~(unsigned)(sp >> 32);

    const int sc = __popc(starts);
    const int nc = __reduce_add_sync(FULL, sc);

    const int b_     = row >> 8;
    const int nn     = row & (N_NEUR - 1);
    const int target = (__ldg(labels + b_) == nn) ? 1 : 0;

    float contrib = 0.0f;
    if (nc > target) {                       // warp-uniform
        if (nc == 1) {
            // single cluster: span max == row max (spikes >= 0, rest < 0)
            #pragma unroll
            for (int d = 16; d > 0; d >>= 1)
                maxall = fmaxf(maxall, __shfl_xor_sync(FULL, maxall, d));
            contrib = maxall;
        } else {
            // ---- cluster table: (spikes before start, start pos)
            const int pc = __popc(m);
            int ipc = pc, isc = sc;          // inclusive scans
            #pragma unroll
            for (int d = 1; d < 32; d <<= 1) {
                int vp = __shfl_up_sync(FULL, ipc, d);
                int vs = __shfl_up_sync(FULL, isc, d);
                if (l >= d) { ipc += vp; isc += vs; }
            }
            const int excl  = ipc - pc;      // spikes before my window
            int c           = isc - sc;      // clusters before my window
            const int S_tot = __shfl_sync(FULL, ipc, 31);

            unsigned sm_ = starts;
            const int tb = l * 32;
            while (sm_) {
                int bit = __ffs(sm_) - 1;
                sm_ &= sm_ - 1;
                int sb = excl + __popc(m & ((1u << bit) - 1u));
                sh_cl[w][c] = ((unsigned)sb << 16) | (unsigned)(tb + bit);
                ++c;
            }
            if (lane0) sh_cl[w][nc] = ((unsigned)S_tot << 16) | (unsigned)T_LEN;
            __syncwarp();

            // smallest cluster, earliest on ties: min over (size<<7 | idx)
            int best = 0x7fffffff;
            for (int c0 = l; c0 < nc; c0 += 32) {
                unsigned a  = sh_cl[w][c0];
                unsigned bn = sh_cl[w][c0 + 1];
                int size = (int)(bn >> 16) - (int)(a >> 16);
                best = min(best, (size << 7) | c0);
            }
            best = __reduce_min_sync(FULL, (unsigned)best);
            const int cstar = best & 127;
            const unsigned a  = sh_cl[w][cstar];
            const unsigned bn = sh_cl[w][cstar + 1];
            const int cb  = (int)(a  & 0xffffu);
            const int ceN = (int)(bn & 0xffffu);     // exclusive end
            const unsigned width = (unsigned)(ceN - cb);

            // re-read only float4 blocks overlapping [cb, ceN) — rare path
            const float4* g4 = (const float4*)rp;
            float smax = NEGINF;
            const int ks = cb >> 7, ke = (ceN - 1) >> 7;
            for (int k = ks; k <= ke; ++k) {
                float4 v = __ldg(g4 + k * 32 + l);
                int t0 = k * 128 + 4 * l;
                if ((unsigned)(t0     - cb) < width) smax = fmaxf(smax, v.x);
                if ((unsigned)(t0 + 1 - cb) < width) smax = fmaxf(smax, v.y);
                if ((unsigned)(t0 + 2 - cb) < width) smax = fmaxf(smax, v.z);
                if ((unsigned)(t0 + 3 - cb) < width) smax = fmaxf(smax, v.w);
            }
            #pragma unroll
            for (int d = 16; d > 0; d >>= 1)
                smax = fmaxf(smax, __shfl_xor_sync(FULL, smax, d));
            contrib = smax;
        }
    } else if (nc == 0 && target) {
        #pragma unroll
        for (int d = 16; d > 0; d >>= 1)
            maxall = fmaxf(maxall, __shfl_xor_sync(FULL, maxall, d));
        contrib = -maxall;
    }

    if (lane0) {
        out[1 + row] = (float)nc;            // spike_output
        warp_contrib[w] = contrib;
    }
    __syncthreads();

    // ---- grid reduction: device accumulator + ticket (graph-replay safe,
    //      single kernel — no separate zeroing launch)
    if (tid == 0) {
        float s = 0.0f;
        #pragma unroll
        for (int i = 0; i < WPB; ++i) s += warp_contrib[i];
        atomicAdd(&g_loss, s);
        __threadfence();
        unsigned t = atomicAdd(&g_tick, 1u);
        if (t == gridDim.x - 1) {            // last block: publish + reset
            __threadfence();
            out[0] = g_loss;
            g_loss = 0.0f;
            g_tick = 0u;
        }
    }
}

extern "C" void kernel_launch(void* const* d_in, const int* in_sizes, int n_in,
                              void* d_out, int out_size) {
    const float* vmem   = (const float*)d_in[0];   // [128,256,1024] f32
    // d_in[1] = vlastmem — unused by the reference forward; deliberately not read
    const int*   labels = (const int*)d_in[2];     // [128] i32
    float*       out    = (float*)d_out;           // [1 + 128*256] f32

    const int total_rows = 128 * 256;              // 32768
    stca_main<<<total_rows / WPB, THREADS>>>(vmem, labels, out);
}